// round 1
// baseline (speedup 1.0000x reference)
#include <cuda_runtime.h>
#include <cuda_bf16.h>
#include <math_constants.h>

// TransferMatrixMethod: B=256, L=64, W=512.
// For each (b,w): M_total = prod_{l=1..62} [[cos(phi), -i sin(phi)/(n+1e-8)],
//                                            [-i n sin(phi), cos(phi)]]
// with phi = n*d*2*pi/lambda. Matrices of the form [[a, ib],[ic, d]] (a,b,c,d real)
// are closed under multiplication -> track 4 real accumulators A,B,C,D where
// M = [[A, iB],[iC, D]].
//
// Epilogue: E = A + i*B*n_sub (+1e-9 on real part), H = D*n_sub + i*C.
// r = (n_in*E - H)/(n_in*E + H);  R = |r|^2  (the Y division cancels).

#define NLAYERS 62
#define LTOT    64
#define WDIM    512

__global__ __launch_bounds__(WDIM)
void tmm_kernel(const float* __restrict__ n_layers,
                const float* __restrict__ d_layers,
                const float* __restrict__ wavelengths,
                float* __restrict__ out)
{
    const int b = blockIdx.x;    // 0..255
    const int w = threadIdx.x;   // 0..511

    __shared__ float s_nd[NLAYERS];
    __shared__ float s_n[NLAYERS];
    __shared__ float s_rinv[NLAYERS];
    __shared__ float s_nin, s_nsub;

    const float* nrow = n_layers + b * LTOT;
    const float* drow = d_layers + b * LTOT;

    if (w < NLAYERS) {
        float nv = nrow[w + 1];
        float dv = drow[w + 1];
        s_nd[w]   = nv * dv;
        s_n[w]    = nv;
        s_rinv[w] = 1.0f / (nv + 1e-8f);
    }
    if (w == NLAYERS)     s_nin  = nrow[0];
    if (w == NLAYERS + 1) s_nsub = nrow[LTOT - 1];
    __syncthreads();

    const float lam = wavelengths[w];
    const float k0  = 6.28318530717958647692f / lam;   // 2*pi/lambda

    float A = 1.0f, B = 0.0f, C = 0.0f, D = 1.0f;

    const float INV_2PI = 0.15915494309189533577f;
    const float TWO_PI  = 6.28318530717958647692f;

    #pragma unroll
    for (int l = 0; l < NLAYERS; ++l) {
        float phi = s_nd[l] * k0;
        // range-reduce into [-pi, pi] so __sincosf stays near-exact
        float t = rintf(phi * INV_2PI);
        phi = fmaf(t, -TWO_PI, phi);

        float sp, cp;
        __sincosf(phi, &sp, &cp);

        const float nl   = s_n[l];
        const float rinv = s_rinv[l];
        const float ns   = nl * sp;     //  n*sin
        const float sr   = sp * rinv;   //  sin/(n+eps)

        // carry <- carry * layer, layer = [[cp, -i*sr],[-i*ns, cp]]
        float nA = fmaf(B,  ns, A * cp);      // A*cp + B*ns
        float nB = fmaf(B,  cp, -A * sr);     // -A*sr + B*cp
        float nC = fmaf(C,  cp, -D * ns);     // C*cp - D*ns
        float nD = fmaf(D,  cp,  C * sr);     // C*sr + D*cp
        A = nA; B = nB; C = nC; D = nD;
    }

    const float nin  = s_nin;
    const float nsub = s_nsub;

    const float Er = A + 1e-9f;
    const float Ei = B * nsub;
    const float Hr = D * nsub;
    const float Hi = C;

    const float numr = fmaf(nin, Er, -Hr);
    const float numi = fmaf(nin, Ei, -Hi);
    const float denr = fmaf(nin, Er,  Hr);
    const float deni = fmaf(nin, Ei,  Hi);

    const float num2 = fmaf(numr, numr, numi * numi);
    const float den2 = fmaf(denr, denr, deni * deni);

    out[b * WDIM + w] = num2 / den2;
}

extern "C" void kernel_launch(void* const* d_in, const int* in_sizes, int n_in,
                              void* d_out, int out_size)
{
    const float* n_layers    = (const float*)d_in[0];  // (256, 64)
    const float* d_layers    = (const float*)d_in[1];  // (256, 64)
    const float* wavelengths = (const float*)d_in[2];  // (512,)
    float* out = (float*)d_out;                        // (256, 512)

    tmm_kernel<<<256, WDIM>>>(n_layers, d_layers, wavelengths, out);
}

// round 2
// speedup vs baseline: 1.2156x; 1.2156x over previous
#include <cuda_runtime.h>
#include <cuda_bf16.h>

// TransferMatrixMethod: B=256, L=64 (62 interior layers), W=512.
// Matrices [[a, ib],[ic, d]] (a,b,c,d real) are closed under multiplication.
// Track P=(A,C), Q=(B,-D) packed as f32x2:
//   P' = cp*P + ns*Q          (ns = n*sin)
//   Q' = cp*Q - sr*P          (sr = sin/(n+1e-8))
// Check: A'=cpA+nsB ok; C'=cpC+ns*(-D)=cpC-nsD ok;
//        B'=cpB-srA ok; (-D)'=cp*(-D)-srC -> D'=cpD+srC ok.
//
// Epilogue (per point): E=(A+1e-9) + i*B*nsub, H = D*nsub + i*C,
//   r=(nin*E-H)/(nin*E+H), R=|num|^2/|den|^2 -> single division.

#define NLAYERS 62
#define LTOT    64
#define WDIM    512
#define TPB     128          // threads per block
#define BPB     (WDIM/TPB)   // blocks per batch row = 4

typedef unsigned long long u64;

__device__ __forceinline__ u64 pack2(float lo, float hi) {
    u64 r;
    asm("mov.b64 %0, {%1, %2};" : "=l"(r) : "f"(lo), "f"(hi));
    return r;
}
__device__ __forceinline__ void unpack2(float& lo, float& hi, u64 v) {
    asm("mov.b64 {%0, %1}, %2;" : "=f"(lo), "=f"(hi) : "l"(v));
}
__device__ __forceinline__ u64 mul2(u64 a, u64 b) {
    u64 r;
    asm("mul.rn.f32x2 %0, %1, %2;" : "=l"(r) : "l"(a), "l"(b));
    return r;
}
__device__ __forceinline__ u64 fma2(u64 a, u64 b, u64 c) {
    u64 r;
    asm("fma.rn.f32x2 %0, %1, %2, %3;" : "=l"(r) : "l"(a), "l"(b), "l"(c));
    return r;
}

__global__ __launch_bounds__(TPB)
void tmm_kernel(const float* __restrict__ n_layers,
                const float* __restrict__ d_layers,
                const float* __restrict__ wavelengths,
                float* __restrict__ out)
{
    const int b = blockIdx.x >> 2;            // 0..255
    const int q = blockIdx.x & 3;             // wavelength quarter
    const int w = q * TPB + threadIdx.x;      // 0..511

    __shared__ float s_nd[NLAYERS];           // n*d per layer
    __shared__ u64   s_n2[NLAYERS];           // {n, n}
    __shared__ u64   s_mr2[NLAYERS];          // {-1/(n+eps), -1/(n+eps)}
    __shared__ float s_nin, s_nsub;

    const float* nrow = n_layers + b * LTOT;
    const float* drow = d_layers + b * LTOT;

    const int t = threadIdx.x;
    if (t < NLAYERS) {
        float nv = nrow[t + 1];
        float dv = drow[t + 1];
        s_nd[t]  = nv * dv;
        s_n2[t]  = pack2(nv, nv);
        float mr = -1.0f / (nv + 1e-8f);
        s_mr2[t] = pack2(mr, mr);
    }
    if (t == NLAYERS)     s_nin  = nrow[0];
    if (t == NLAYERS + 1) s_nsub = nrow[LTOT - 1];
    __syncthreads();

    const float lam     = wavelengths[w];
    const float inv_lam = 1.0f / lam;               // = k0/(2pi)
    const float TWO_PI  = 6.28318530717958647692f;

    u64 P = pack2(1.0f, 0.0f);    // (A, C)
    u64 Q = pack2(0.0f, -1.0f);   // (B, -D)

    #pragma unroll
    for (int l = 0; l < NLAYERS; ++l) {
        // phi = nd * 2pi / lam, range-reduced to [-pi, pi]
        float psi = s_nd[l] * inv_lam;          // phi / 2pi
        float tt  = rintf(psi);
        float phi = (psi - tt) * TWO_PI;

        float sp, cp;
        __sincosf(phi, &sp, &cp);

        u64 sp2  = pack2(sp, sp);
        u64 cp2  = pack2(cp, cp);
        u64 ns2  = mul2(sp2, s_n2[l]);          // {n*sin, n*sin}
        u64 msr2 = mul2(sp2, s_mr2[l]);         // {-sin/(n+eps), ...}

        u64 Pcp = mul2(P, cp2);
        u64 Qcp = mul2(Q, cp2);
        u64 nP  = fma2(Q, ns2,  Pcp);           // cp*P + ns*Q
        u64 nQ  = fma2(P, msr2, Qcp);           // cp*Q - sr*P
        P = nP; Q = nQ;
    }

    float A, C, B, mD;
    unpack2(A, C, P);
    unpack2(B, mD, Q);
    const float D = -mD;

    const float nin  = s_nin;
    const float nsub = s_nsub;

    const float Er = A + 1e-9f;
    const float Ei = B * nsub;
    const float Hr = D * nsub;
    const float Hi = C;

    const float numr = fmaf(nin, Er, -Hr);
    const float numi = fmaf(nin, Ei, -Hi);
    const float denr = fmaf(nin, Er,  Hr);
    const float deni = fmaf(nin, Ei,  Hi);

    const float num2 = fmaf(numr, numr, numi * numi);
    const float den2 = fmaf(denr, denr, deni * deni);

    out[b * WDIM + w] = num2 / den2;
}

extern "C" void kernel_launch(void* const* d_in, const int* in_sizes, int n_in,
                              void* d_out, int out_size)
{
    const float* n_layers    = (const float*)d_in[0];  // (256, 64)
    const float* d_layers    = (const float*)d_in[1];  // (256, 64)
    const float* wavelengths = (const float*)d_in[2];  // (512,)
    float* out = (float*)d_out;                        // (256, 512)

    tmm_kernel<<<256 * BPB, TPB>>>(n_layers, d_layers, wavelengths, out);
}